// round 15
// baseline (speedup 1.0000x reference)
#include <cuda_runtime.h>
#include <cuda_fp16.h>
#include <stdint.h>
#include <math.h>

#define T_TOK 4096
#define H_DIM 1024
#define N_EXP 8
#define I_DIM 2048
#define IS_DIM 4096
#define NSLOT (2 * T_TOK)

using f16 = __half;

// ---------------- scratch (static device globals; no runtime alloc) --------
__device__ int   g_cnt[N_EXP];
__device__ int   g_off[N_EXP];
__device__ int   g_tok[N_EXP * T_TOK];
__device__ float g_wt [N_EXP * T_TOK];
__device__ int   g_slottok[NSLOT];
__device__ float g_slotwt [NSLOT];

// fp16 operands. x split hi/lo; weights single fp16; activations single fp16.
__device__ __align__(16) f16 xh_ [T_TOK * H_DIM];
__device__ __align__(16) f16 xl_ [T_TOK * H_DIM];
__device__ __align__(16) f16 Wg_ [N_EXP * H_DIM * I_DIM];
__device__ __align__(16) f16 Wu_ [N_EXP * H_DIM * I_DIM];
__device__ __align__(16) f16 Wd_ [N_EXP * I_DIM * H_DIM];
__device__ __align__(16) f16 Sg_ [H_DIM * IS_DIM];
__device__ __align__(16) f16 Su_ [H_DIM * IS_DIM];
__device__ __align__(16) f16 Sd_ [IS_DIM * H_DIM];
__device__ __align__(16) f16 act_ [NSLOT * I_DIM];
__device__ __align__(16) f16 sact_[T_TOK * IS_DIM];

// ---------------- helpers ---------------------------------------------------
__device__ __forceinline__ unsigned short f2hu(float f) {
    f16 h = __float2half(f);
    return reinterpret_cast<unsigned short&>(h);
}
__device__ __forceinline__ float hu2f(unsigned short u) {
    f16 h = reinterpret_cast<f16&>(u);
    return __half2float(h);
}
__device__ __forceinline__ uint32_t s2u(const void* p) {
    return (uint32_t)__cvta_generic_to_shared(p);
}
__device__ __forceinline__ void cp16(void* smem, const void* gmem) {
    asm volatile("cp.async.cg.shared.global [%0], [%1], 16;"
                 :: "r"(s2u(smem)), "l"(gmem));
}
#define CP_COMMIT()  asm volatile("cp.async.commit_group;" ::: "memory")
#define CP_WAIT1()   asm volatile("cp.async.wait_group 1;" ::: "memory")
#define CP_WAIT0()   asm volatile("cp.async.wait_group 0;" ::: "memory")

// ---------------- init ------------------------------------------------------
__global__ void k_init(float* out, int out_size) {
    int tid = threadIdx.x;
    if (tid < N_EXP) g_cnt[tid] = 0;
    for (int i = T_TOK * H_DIM + tid; i < out_size; i += blockDim.x) out[i] = 0.f;
}

// ---------------- fp32 -> fp16 hi/lo split (x) ------------------------------
__global__ void k_cvt_x(const float* __restrict__ s) {
    long n4 = (long)T_TOK * H_DIM / 4;
    for (long i = (long)blockIdx.x * blockDim.x + threadIdx.x; i < n4;
         i += (long)gridDim.x * blockDim.x) {
        float4 v = ((const float4*)s)[i];
        ushort4 h, l;
        h.x = f2hu(v.x); l.x = f2hu(v.x - hu2f(h.x));
        h.y = f2hu(v.y); l.y = f2hu(v.y - hu2f(h.y));
        h.z = f2hu(v.z); l.z = f2hu(v.z - hu2f(h.z));
        h.w = f2hu(v.w); l.w = f2hu(v.w - hu2f(h.w));
        ((ushort4*)xh_)[i] = h;
        ((ushort4*)xl_)[i] = l;
    }
}

// ---------------- fp32 -> fp16 single (weights) -----------------------------
__device__ __forceinline__ void cvt1_body(const float* __restrict__ src,
                                          f16* __restrict__ dst, long n4) {
    for (long i = (long)blockIdx.x * blockDim.x + threadIdx.x; i < n4;
         i += (long)gridDim.x * blockDim.x) {
        float4 v = ((const float4*)src)[i];
        ushort4 h;
        h.x = f2hu(v.x); h.y = f2hu(v.y); h.z = f2hu(v.z); h.w = f2hu(v.w);
        ((ushort4*)dst)[i] = h;
    }
}
__global__ void k_cvt_wg(const float* s){ cvt1_body(s, Wg_, (long)N_EXP * H_DIM * I_DIM / 4); }
__global__ void k_cvt_wu(const float* s){ cvt1_body(s, Wu_, (long)N_EXP * H_DIM * I_DIM / 4); }
__global__ void k_cvt_wd(const float* s){ cvt1_body(s, Wd_, (long)N_EXP * I_DIM * H_DIM / 4); }
__global__ void k_cvt_sg(const float* s){ cvt1_body(s, Sg_, (long)H_DIM * IS_DIM / 4); }
__global__ void k_cvt_su(const float* s){ cvt1_body(s, Su_, (long)H_DIM * IS_DIM / 4); }
__global__ void k_cvt_sd(const float* s){ cvt1_body(s, Sd_, (long)IS_DIM * H_DIM / 4); }

// ---------------- router: logits, top-2, softmax, expert lists --------------
__global__ __launch_bounds__(256) void k_router(const float* __restrict__ x,
                                                const float* __restrict__ rw) {
    int t = blockIdx.x;
    __shared__ float sx[H_DIM];
    __shared__ float slog[N_EXP];
    const float* xr = x + (size_t)t * H_DIM;
    for (int i = threadIdx.x; i < H_DIM; i += 256) sx[i] = xr[i];
    __syncthreads();
    int w = threadIdx.x >> 5, lane = threadIdx.x & 31;
    if (w < N_EXP) {
        const float* r = rw + w * H_DIM;
        float s = 0.f;
        for (int h = lane; h < H_DIM; h += 32) s += sx[h] * r[h];
        #pragma unroll
        for (int o = 16; o; o >>= 1) s += __shfl_xor_sync(0xffffffffu, s, o);
        if (!lane) slog[w] = s;
    }
    __syncthreads();
    if (threadIdx.x == 0) {
        int b0 = 0; float v0 = slog[0];
        #pragma unroll
        for (int e = 1; e < N_EXP; e++) if (slog[e] > v0) { v0 = slog[e]; b0 = e; }
        int b1 = -1; float v1 = -3.4e38f;
        #pragma unroll
        for (int e = 0; e < N_EXP; e++) if (e != b0 && slog[e] > v1) { v1 = slog[e]; b1 = e; }
        float e1 = expf(v1 - v0);
        float inv = 1.f / (1.f + e1);
        int s0 = atomicAdd(&g_cnt[b0], 1);
        g_tok[b0 * T_TOK + s0] = t;  g_wt[b0 * T_TOK + s0] = inv;
        int s1 = atomicAdd(&g_cnt[b1], 1);
        g_tok[b1 * T_TOK + s1] = t;  g_wt[b1 * T_TOK + s1] = e1 * inv;
    }
}

__global__ void k_off() {
    if (threadIdx.x == 0) {
        int o = 0;
        #pragma unroll
        for (int e = 0; e < N_EXP; e++) { g_off[e] = o; o += g_cnt[e]; }
    }
}

__global__ void k_fill() {
    int e = blockIdx.x;
    int cnt = g_cnt[e], off = g_off[e];
    for (int i = threadIdx.x; i < cnt; i += blockDim.x) {
        g_slottok[off + i] = g_tok[e * T_TOK + i];
        g_slotwt [off + i] = g_wt [e * T_TOK + i];
    }
}

#define SA_LD 40
#define SB_LD 136
#define SD_LD 72
#define SA_STAGE (128 * SA_LD)
#define SB_STAGE (32 * SB_LD)
#define SD_STAGE (32 * SD_LD)
#define NSTAGE 3
#define GU_SMEM ((NSTAGE * (SA_STAGE + 2 * SD_STAGE)) * 2)
#define DN_SMEM ((NSTAGE * (SA_STAGE + SB_STAGE)) * 2)

// ============================================================================
// Fused gate+up GEMM + SwiGLU -> single-fp16 activations.
// Block tile M=128, dual N=64 (Wg and Wu share the A tile). BK=32 fp16,
// 2 K-segments: [xh*B | xl*B]. cp.async 3-stage ring, ONE barrier per chunk.
// 8 warps (4M x 2N), warp tile 32x32 per matrix.
// mode 0: shared expert (dense x -> sact). mode 1: expert e (gathered).
// ============================================================================
__global__ __launch_bounds__(256) void k_gu(int mode) {
    int e = 0, cnt = T_TOK, off = 0;
    if (mode) {
        e = blockIdx.z;
        cnt = g_cnt[e];
        off = g_off[e];
    }
    int m0 = blockIdx.y * 128;
    if (m0 >= cnt) return;
    int n0 = blockIdx.x * 64;

    const f16 *Bg, *Bu;
    f16 *D;
    int ldb, ldc;
    if (mode) {
        long wb = (long)e * H_DIM * I_DIM;
        Bg = Wg_ + wb; Bu = Wu_ + wb;
        D = act_; ldb = I_DIM; ldc = I_DIM;
    } else {
        Bg = Sg_; Bu = Su_;
        D = sact_; ldb = IS_DIM; ldc = IS_DIM;
    }

    extern __shared__ f16 smem_[];
    f16* sA  = smem_;
    f16* sBg = smem_ + NSTAGE * SA_STAGE;
    f16* sBu = sBg  + NSTAGE * SD_STAGE;

    const int tid = threadIdx.x;
    const int lane = tid & 31, wid = tid >> 5;
    const int wm = wid & 3, wn = wid >> 2;
    const int ar = tid >> 1, ac = (tid & 1) << 4;
    const int br = tid >> 3, bc = (tid & 7) << 3;

    int mrow = m0 + ar; if (mrow >= cnt) mrow = cnt - 1;
    int rowidx = mode ? g_tok[e * T_TOK + mrow] : mrow;
    long aoff = (long)rowidx * H_DIM + ac;
    long boff = (long)br * ldb + n0 + bc;

    const int kseg = H_DIM >> 5;
    const int nk = 2 * kseg;

    float accg[32], accu[32];
    #pragma unroll
    for (int i = 0; i < 32; i++) { accg[i] = 0.f; accu[i] = 0.f; }

    auto issue = [&](int kb) {
        int s  = kb / kseg;
        int kl = (kb - s * kseg) << 5;
        const f16* ap = (s ? xl_ : xh_) + aoff + kl;
        const f16* gp = Bg + boff + (long)kl * ldb;
        const f16* up = Bu + boff + (long)kl * ldb;
        int st = kb % NSTAGE;
        f16* dA = sA + st * SA_STAGE + ar * SA_LD + ac;
        cp16(dA, ap);
        cp16(dA + 8, ap + 8);
        cp16(sBg + st * SD_STAGE + br * SD_LD + bc, gp);
        cp16(sBu + st * SD_STAGE + br * SD_LD + bc, up);
        CP_COMMIT();
    };

    issue(0);
    issue(1);
    for (int kb = 0; kb < nk; kb++) {
        if (kb + 1 < nk) CP_WAIT1(); else CP_WAIT0();
        __syncthreads();
        if (kb + 2 < nk) issue(kb + 2);
        int st = kb % NSTAGE;
        const f16* cA = sA  + st * SA_STAGE;
        const f16* cG = sBg + st * SD_STAGE;
        const f16* cU = sBu + st * SD_STAGE;
        #pragma unroll
        for (int ks = 0; ks < 2; ks++) {
            uint32_t af[2][4];
            #pragma unroll
            for (int mt = 0; mt < 2; mt++) {
                int row = wm * 32 + mt * 16 + (lane & 15);
                int col = ks * 16 + ((lane >> 4) << 3);
                uint32_t ad = s2u(&cA[row * SA_LD + col]);
                asm volatile("ldmatrix.sync.aligned.m8n8.x4.shared.b16 {%0,%1,%2,%3}, [%4];"
                    : "=r"(af[mt][0]), "=r"(af[mt][1]), "=r"(af[mt][2]), "=r"(af[mt][3])
                    : "r"(ad));
            }
            uint32_t bg[4][2], bu[4][2];
            #pragma unroll
            for (int nt = 0; nt < 2; nt++) {
                int row = ks * 16 + (lane & 15);
                int col = wn * 32 + nt * 16 + ((lane >> 4) << 3);
                uint32_t gd = s2u(&cG[row * SD_LD + col]);
                asm volatile("ldmatrix.sync.aligned.m8n8.x4.trans.shared.b16 {%0,%1,%2,%3}, [%4];"
                    : "=r"(bg[nt*2][0]), "=r"(bg[nt*2][1]),
                      "=r"(bg[nt*2+1][0]), "=r"(bg[nt*2+1][1])
                    : "r"(gd));
                uint32_t ud = s2u(&cU[row * SD_LD + col]);
                asm volatile("ldmatrix.sync.aligned.m8n8.x4.trans.shared.b16 {%0,%1,%2,%3}, [%4];"
                    : "=r"(bu[nt*2][0]), "=r"(bu[nt*2][1]),
                      "=r"(bu[nt*2+1][0]), "=r"(bu[nt*2+1][1])
                    : "r"(ud));
            }
            #pragma unroll
            for (int mt = 0; mt < 2; mt++)
                #pragma unroll
                for (int nt = 0; nt < 4; nt++) {
                    float* cg = accg + (mt * 4 + nt) * 4;
                    asm volatile("mma.sync.aligned.m16n8k16.row.col.f32.f16.f16.f32 "
                        "{%0,%1,%2,%3},{%4,%5,%6,%7},{%8,%9},{%0,%1,%2,%3};"
                        : "+f"(cg[0]), "+f"(cg[1]), "+f"(cg[2]), "+f"(cg[3])
                        : "r"(af[mt][0]), "r"(af[mt][1]), "r"(af[mt][2]), "r"(af[mt][3]),
                          "r"(bg[nt][0]), "r"(bg[nt][1]));
                    float* cu = accu + (mt * 4 + nt) * 4;
                    asm volatile("mma.sync.aligned.m16n8k16.row.col.f32.f16.f16.f32 "
                        "{%0,%1,%2,%3},{%4,%5,%6,%7},{%8,%9},{%0,%1,%2,%3};"
                        : "+f"(cu[0]), "+f"(cu[1]), "+f"(cu[2]), "+f"(cu[3])
                        : "r"(af[mt][0]), "r"(af[mt][1]), "r"(af[mt][2]), "r"(af[mt][3]),
                          "r"(bu[nt][0]), "r"(bu[nt][1]));
                }
        }
    }

    // epilogue: v = [w*] silu(g) * u ; store single fp16.
    #pragma unroll
    for (int mt = 0; mt < 2; mt++) {
        int l0 = wm * 32 + mt * 16 + (lane >> 2);
        int m_a = m0 + l0, m_b = m0 + l0 + 8;
        bool va = m_a < cnt, vb = m_b < cnt;
        float wa = 1.f, wb_ = 1.f;
        if (mode) {
            wa  = va ? g_slotwt[off + m_a] : 0.f;
            wb_ = vb ? g_slotwt[off + m_b] : 0.f;
        }
        #pragma unroll
        for (int nt = 0; nt < 4; nt++) {
            float* cg = accg + (mt * 4 + nt) * 4;
            float* cu = accu + (mt * 4 + nt) * 4;
            int col = n0 + wn * 32 + nt * 8 + ((lane & 3) << 1);
            if (va) {
                float g0 = cg[0], g1 = cg[1];
                float v0 = wa * (g0 / (1.f + expf(-g0))) * cu[0];
                float v1 = wa * (g1 / (1.f + expf(-g1))) * cu[1];
                long r = (long)(off + m_a) * ldc + col;
                *(ushort2*)(D + r) = make_ushort2(f2hu(v0), f2hu(v1));
            }
            if (vb) {
                float g2 = cg[2], g3 = cg[3];
                float v2 = wb_ * (g2 / (1.f + expf(-g2))) * cu[2];
                float v3 = wb_ * (g3 / (1.f + expf(-g3))) * cu[3];
                long r = (long)(off + m_b) * ldc + col;
                *(ushort2*)(D + r) = make_ushort2(f2hu(v2), f2hu(v3));
            }
        }
    }
}

// ============================================================================
// Single-segment GEMM core (down projections). Block 128x128, BK=32,
// cp.async 3-stage ring, ONE barrier per chunk. 8 warps (4M x 2N), warp 32x64.
// ============================================================================
__device__ __forceinline__ void gemm_core(
    const f16* __restrict__ A, long aoff,
    const f16* __restrict__ B, int ldb, long boff,
    int K, float* acc, f16* sA, f16* sB)
{
    const int tid = threadIdx.x;
    const int lane = tid & 31, wid = tid >> 5;
    const int wm = wid & 3, wn = wid >> 2;
    const int ar = tid >> 1, ac = (tid & 1) << 4;
    const int br = tid >> 3, bc = (tid & 7) << 4;
    const int nk = K >> 5;

    auto issue = [&](int kb) {
        int kl = kb << 5;
        const f16* ap = A + aoff + kl;
        const f16* bp = B + boff + (long)kl * ldb;
        int st = kb % NSTAGE;
        f16* dA = sA + st * SA_STAGE + ar * SA_LD + ac;
        cp16(dA, ap);
        cp16(dA + 8, ap + 8);
        f16* dB = sB + st * SB_STAGE + br * SB_LD + bc;
        cp16(dB, bp);
        cp16(dB + 8, bp + 8);
        CP_COMMIT();
    };

    issue(0);
    issue(1);
    for (int kb = 0; kb < nk; kb++) {
        if (kb + 1 < nk) CP_WAIT1(); else CP_WAIT0();
        __syncthreads();
        if (kb + 2 < nk) issue(kb + 2);
        int st = kb % NSTAGE;
        const f16* cA = sA + st * SA_STAGE;
        const f16* cB = sB + st * SB_STAGE;
        #pragma unroll
        for (int ks = 0; ks < 2; ks++) {
            uint32_t af[2][4];
            #pragma unroll
            for (int mt = 0; mt < 2; mt++) {
                int row = wm * 32 + mt * 16 + (lane & 15);
                int col = ks * 16 + ((lane >> 4) << 3);
                uint32_t ad = s2u(&cA[row * SA_LD + col]);
                asm volatile("ldmatrix.sync.aligned.m8n8.x4.shared.b16 {%0,%1,%2,%3}, [%4];"
                    : "=r"(af[mt][0]), "=r"(af[mt][1]), "=r"(af[mt][2]), "=r"(af[mt][3])
                    : "r"(ad));
            }
            uint32_t bfr[8][2];
            #pragma unroll
            for (int nt = 0; nt < 4; nt++) {
                int row = ks * 16 + (lane & 15);
                int col = wn * 64 + nt * 16 + ((lane >> 4) << 3);
                uint32_t bd = s2u(&cB[row * SB_LD + col]);
                asm volatile("ldmatrix.sync.aligned.m8n8.x4.trans.shared.b16 {%0,%1,%2,%3}, [%4];"
                    : "=r"(bfr[nt*2][0]), "=r"(bfr[nt*2][1]),
                      "=r"(bfr[nt*2+1][0]), "=r"(bfr[nt*2+1][1])
                    : "r"(bd));
            }
            #pragma unroll
            for (int mt = 0; mt < 2; mt++)
                #pragma unroll
                for (int nt = 0; nt < 8; nt++) {
                    float* c = acc + (mt * 8 + nt) * 4;
                    asm volatile("mma.sync.aligned.m16n8k16.row.col.f32.f16.f16.f32 "
                        "{%0,%1,%2,%3},{%4,%5,%6,%7},{%8,%9},{%0,%1,%2,%3};"
                        : "+f"(c[0]), "+f"(c[1]), "+f"(c[2]), "+f"(c[3])
                        : "r"(af[mt][0]), "r"(af[mt][1]), "r"(af[mt][2]), "r"(af[mt][3]),
                          "r"(bfr[nt][0]), "r"(bfr[nt][1]));
                }
        }
    }
}

// ---------------- shared expert down GEMM: out = sact @ Sd ------------------
__global__ __launch_bounds__(256) void k_sdown(float* __restrict__ outp) {
    extern __shared__ f16 smem_[];
    f16* sA = smem_;
    f16* sB = smem_ + NSTAGE * SA_STAGE;
    int m0 = blockIdx.y * 128, n0 = blockIdx.x * 128;
    int tid = threadIdx.x;
    int ar = tid >> 1, ac = (tid & 1) << 4;
    int br = tid >> 3, bc = (tid & 7) << 4;
    long aoff = (long)(m0 + ar) * IS_DIM + ac;
    long boff = (long)br * H_DIM + n0 + bc;
    float acc[64];
    #pragma unroll
    for (int i = 0; i < 64; i++) acc[i] = 0.f;

    gemm_core(sact_, aoff, Sd_, H_DIM, boff, IS_DIM, acc, sA, sB);

    int lane = tid & 31, wid = tid >> 5, wm = wid & 3, wn = wid >> 2;
    #pragma unroll
    for (int mt = 0; mt < 2; mt++) {
        int l0 = wm * 32 + mt * 16 + (lane >> 2);
        #pragma unroll
        for (int nt = 0; nt < 8; nt++) {
            float* c = acc + (mt * 8 + nt) * 4;
            int col = n0 + wn * 64 + nt * 8 + ((lane & 3) << 1);
            long r0 = (long)(m0 + l0) * H_DIM + col;
            long r1 = (long)(m0 + l0 + 8) * H_DIM + col;
            outp[r0] = c[0]; outp[r0 + 1] = c[1];
            outp[r1] = c[2]; outp[r1 + 1] = c[3];
        }
    }
}

// ---------------- expert down GEMM (contig slot A, atomic scatter C) --------
__global__ __launch_bounds__(256) void k_edown(float* __restrict__ out) {
    int e = blockIdx.z;
    int cnt = g_cnt[e];
    int m0 = blockIdx.y * 128;
    if (m0 >= cnt) return;
    int off = g_off[e];
    int n0 = blockIdx.x * 128;

    const f16* B = Wd_ + (long)e * I_DIM * H_DIM;

    extern __shared__ f16 smem_[];
    f16* sA = smem_;
    f16* sB = smem_ + NSTAGE * SA_STAGE;
    int tid = threadIdx.x;
    int ar = tid >> 1, ac = (tid & 1) << 4;
    int br = tid >> 3, bc = (tid & 7) << 4;
    int slot = off + m0 + ar; if (slot >= NSLOT) slot = NSLOT - 1;
    long aoff = (long)slot * I_DIM + ac;
    long boff = (long)br * H_DIM + n0 + bc;
    float acc[64];
    #pragma unroll
    for (int i = 0; i < 64; i++) acc[i] = 0.f;

    gemm_core(act_, aoff, B, H_DIM, boff, I_DIM, acc, sA, sB);

    int lane = tid & 31, wid = tid >> 5, wm = wid & 3, wn = wid >> 2;
    #pragma unroll
    for (int mt = 0; mt < 2; mt++) {
        int l0 = wm * 32 + mt * 16 + (lane >> 2);
        int t0 = (m0 + l0)     < cnt ? g_slottok[off + m0 + l0]     : -1;
        int t1 = (m0 + l0 + 8) < cnt ? g_slottok[off + m0 + l0 + 8] : -1;
        #pragma unroll
        for (int nt = 0; nt < 8; nt++) {
            float* c = acc + (mt * 8 + nt) * 4;
            int col = n0 + wn * 64 + nt * 8 + ((lane & 3) << 1);
            if (t0 >= 0) {
                float* d = out + (long)t0 * H_DIM + col;
                atomicAdd(d, c[0]); atomicAdd(d + 1, c[1]);
            }
            if (t1 >= 0) {
                float* d = out + (long)t1 * H_DIM + col;
                atomicAdd(d, c[2]); atomicAdd(d + 1, c[3]);
            }
        }
    }
}

// ---------------- launch ----------------------------------------------------
extern "C" void kernel_launch(void* const* d_in, const int* in_sizes, int n_in,
                              void* d_out, int out_size) {
    const float* x  = (const float*)d_in[0];
    const float* rw = (const float*)d_in[1];
    const float* Wg = (const float*)d_in[2];
    const float* Wu = (const float*)d_in[3];
    const float* Wd = (const float*)d_in[4];
    const float* Sg = (const float*)d_in[5];
    const float* Su = (const float*)d_in[6];
    const float* Sd = (const float*)d_in[7];
    float* out = (float*)d_out;

    cudaFuncSetAttribute(k_gu,    cudaFuncAttributeMaxDynamicSharedMemorySize, GU_SMEM);
    cudaFuncSetAttribute(k_sdown, cudaFuncAttributeMaxDynamicSharedMemorySize, DN_SMEM);
    cudaFuncSetAttribute(k_edown, cudaFuncAttributeMaxDynamicSharedMemorySize, DN_SMEM);

    k_init<<<1, 256>>>(out, out_size);

    k_cvt_x <<<2048, 256>>>(x);
    k_cvt_wg<<<4096, 256>>>(Wg);
    k_cvt_wu<<<4096, 256>>>(Wu);
    k_cvt_wd<<<4096, 256>>>(Wd);
    k_cvt_sg<<<2048, 256>>>(Sg);
    k_cvt_su<<<2048, 256>>>(Su);
    k_cvt_sd<<<2048, 256>>>(Sd);

    k_router<<<T_TOK, 256>>>(x, rw);
    k_off<<<1, 32>>>();
    k_fill<<<N_EXP, 256>>>();

    // fused gate/up + swiglu -> single-fp16 activations
    k_gu<<<dim3(IS_DIM / 64, T_TOK / 128), 256, GU_SMEM>>>(0);              // shared
    k_gu<<<dim3(I_DIM / 64, T_TOK / 128, N_EXP), 256, GU_SMEM>>>(1);        // experts

    // single-segment down projections: shared writes out; experts accumulate
    k_sdown<<<dim3(H_DIM / 128, T_TOK / 128), 256, DN_SMEM>>>(out);
    k_edown<<<dim3(H_DIM / 128, T_TOK / 128, N_EXP), 256, DN_SMEM>>>(out);
}

// round 17
// speedup vs baseline: 1.5078x; 1.5078x over previous
#include <cuda_runtime.h>
#include <cuda_fp16.h>
#include <stdint.h>
#include <math.h>

#define T_TOK 4096
#define H_DIM 1024
#define N_EXP 8
#define I_DIM 2048
#define IS_DIM 4096
#define NSLOT (2 * T_TOK)

using f16 = __half;

// ---------------- scratch (static device globals; no runtime alloc) --------
__device__ int   g_cnt[N_EXP];
__device__ int   g_off[N_EXP];
__device__ int   g_tok[N_EXP * T_TOK];
__device__ float g_wt [N_EXP * T_TOK];
__device__ int   g_slottok[NSLOT];
__device__ float g_slotwt [NSLOT];

// fp16 operands. x split hi/lo; weights single fp16; activations single fp16.
__device__ __align__(16) f16 xh_ [T_TOK * H_DIM];
__device__ __align__(16) f16 xl_ [T_TOK * H_DIM];
__device__ __align__(16) f16 Wg_ [N_EXP * H_DIM * I_DIM];
__device__ __align__(16) f16 Wu_ [N_EXP * H_DIM * I_DIM];
__device__ __align__(16) f16 Wd_ [N_EXP * I_DIM * H_DIM];
__device__ __align__(16) f16 Sg_ [H_DIM * IS_DIM];
__device__ __align__(16) f16 Su_ [H_DIM * IS_DIM];
__device__ __align__(16) f16 Sd_ [IS_DIM * H_DIM];
__device__ __align__(16) f16 act_ [NSLOT * I_DIM];
__device__ __align__(16) f16 sact_[T_TOK * IS_DIM];

// ---------------- helpers ---------------------------------------------------
__device__ __forceinline__ unsigned short f2hu(float f) {
    f16 h = __float2half(f);
    return reinterpret_cast<unsigned short&>(h);
}
__device__ __forceinline__ float hu2f(unsigned short u) {
    f16 h = reinterpret_cast<f16&>(u);
    return __half2float(h);
}
__device__ __forceinline__ uint32_t s2u(const void* p) {
    return (uint32_t)__cvta_generic_to_shared(p);
}
__device__ __forceinline__ void cp16(void* smem, const void* gmem) {
    asm volatile("cp.async.cg.shared.global [%0], [%1], 16;"
                 :: "r"(s2u(smem)), "l"(gmem));
}
#define CP_COMMIT()  asm volatile("cp.async.commit_group;" ::: "memory")
#define CP_WAIT1()   asm volatile("cp.async.wait_group 1;" ::: "memory")
#define CP_WAIT0()   asm volatile("cp.async.wait_group 0;" ::: "memory")

// ---------------- init ------------------------------------------------------
__global__ void k_init(float* out, int out_size) {
    int tid = threadIdx.x;
    if (tid < N_EXP) g_cnt[tid] = 0;
    for (int i = T_TOK * H_DIM + tid; i < out_size; i += blockDim.x) out[i] = 0.f;
}

// ---------------- fp32 -> fp16 hi/lo split (x) ------------------------------
__global__ void k_cvt_x(const float* __restrict__ s) {
    long n4 = (long)T_TOK * H_DIM / 4;
    for (long i = (long)blockIdx.x * blockDim.x + threadIdx.x; i < n4;
         i += (long)gridDim.x * blockDim.x) {
        float4 v = ((const float4*)s)[i];
        ushort4 h, l;
        h.x = f2hu(v.x); l.x = f2hu(v.x - hu2f(h.x));
        h.y = f2hu(v.y); l.y = f2hu(v.y - hu2f(h.y));
        h.z = f2hu(v.z); l.z = f2hu(v.z - hu2f(h.z));
        h.w = f2hu(v.w); l.w = f2hu(v.w - hu2f(h.w));
        ((ushort4*)xh_)[i] = h;
        ((ushort4*)xl_)[i] = l;
    }
}

// ---------------- fp32 -> fp16 single (weights) -----------------------------
__device__ __forceinline__ void cvt1_body(const float* __restrict__ src,
                                          f16* __restrict__ dst, long n4) {
    for (long i = (long)blockIdx.x * blockDim.x + threadIdx.x; i < n4;
         i += (long)gridDim.x * blockDim.x) {
        float4 v = ((const float4*)src)[i];
        ushort4 h;
        h.x = f2hu(v.x); h.y = f2hu(v.y); h.z = f2hu(v.z); h.w = f2hu(v.w);
        ((ushort4*)dst)[i] = h;
    }
}
__global__ void k_cvt_wg(const float* s){ cvt1_body(s, Wg_, (long)N_EXP * H_DIM * I_DIM / 4); }
__global__ void k_cvt_wu(const float* s){ cvt1_body(s, Wu_, (long)N_EXP * H_DIM * I_DIM / 4); }
__global__ void k_cvt_wd(const float* s){ cvt1_body(s, Wd_, (long)N_EXP * I_DIM * H_DIM / 4); }
__global__ void k_cvt_sg(const float* s){ cvt1_body(s, Sg_, (long)H_DIM * IS_DIM / 4); }
__global__ void k_cvt_su(const float* s){ cvt1_body(s, Su_, (long)H_DIM * IS_DIM / 4); }
__global__ void k_cvt_sd(const float* s){ cvt1_body(s, Sd_, (long)IS_DIM * H_DIM / 4); }

// ---------------- router: logits, top-2, softmax, expert lists --------------
__global__ __launch_bounds__(256) void k_router(const float* __restrict__ x,
                                                const float* __restrict__ rw) {
    int t = blockIdx.x;
    __shared__ float sx[H_DIM];
    __shared__ float slog[N_EXP];
    const float* xr = x + (size_t)t * H_DIM;
    for (int i = threadIdx.x; i < H_DIM; i += 256) sx[i] = xr[i];
    __syncthreads();
    int w = threadIdx.x >> 5, lane = threadIdx.x & 31;
    if (w < N_EXP) {
        const float* r = rw + w * H_DIM;
        float s = 0.f;
        for (int h = lane; h < H_DIM; h += 32) s += sx[h] * r[h];
        #pragma unroll
        for (int o = 16; o; o >>= 1) s += __shfl_xor_sync(0xffffffffu, s, o);
        if (!lane) slog[w] = s;
    }
    __syncthreads();
    if (threadIdx.x == 0) {
        int b0 = 0; float v0 = slog[0];
        #pragma unroll
        for (int e = 1; e < N_EXP; e++) if (slog[e] > v0) { v0 = slog[e]; b0 = e; }
        int b1 = -1; float v1 = -3.4e38f;
        #pragma unroll
        for (int e = 0; e < N_EXP; e++) if (e != b0 && slog[e] > v1) { v1 = slog[e]; b1 = e; }
        float e1 = expf(v1 - v0);
        float inv = 1.f / (1.f + e1);
        int s0 = atomicAdd(&g_cnt[b0], 1);
        g_tok[b0 * T_TOK + s0] = t;  g_wt[b0 * T_TOK + s0] = inv;
        int s1 = atomicAdd(&g_cnt[b1], 1);
        g_tok[b1 * T_TOK + s1] = t;  g_wt[b1 * T_TOK + s1] = e1 * inv;
    }
}

__global__ void k_off() {
    if (threadIdx.x == 0) {
        int o = 0;
        #pragma unroll
        for (int e = 0; e < N_EXP; e++) { g_off[e] = o; o += g_cnt[e]; }
    }
}

__global__ void k_fill() {
    int e = blockIdx.x;
    int cnt = g_cnt[e], off = g_off[e];
    for (int i = threadIdx.x; i < cnt; i += blockDim.x) {
        g_slottok[off + i] = g_tok[e * T_TOK + i];
        g_slotwt [off + i] = g_wt [e * T_TOK + i];
    }
}

#define SA_LD 40
#define SB_LD 136
#define SD_LD 72
#define SA_STAGE (128 * SA_LD)
#define SB_STAGE (32 * SB_LD)
#define SD_STAGE (32 * SD_LD)
#define NSTAGE 3
#define GU_SMEM ((NSTAGE * (SA_STAGE + 2 * SD_STAGE)) * 2)
#define DN_SMEM ((NSTAGE * (SA_STAGE + SB_STAGE)) * 2)

// ============================================================================
// Fused gate+up GEMM + SwiGLU -> single-fp16 activations.
// Block tile M=128, dual N=64 (Wg and Wu share the A tile). BK=32 fp16,
// 2 K-segments: [xh*B | xl*B]. cp.async 3-stage ring, ONE barrier per chunk.
// 8 warps (4M x 2N), warp tile 32x32 per matrix.
// mode 0: shared expert (dense x -> sact). mode 1: expert e (gathered).
// ============================================================================
__global__ __launch_bounds__(256) void k_gu(int mode) {
    int e = 0, cnt = T_TOK, off = 0;
    if (mode) {
        e = blockIdx.z;
        cnt = g_cnt[e];
        off = g_off[e];
    }
    int m0 = blockIdx.y * 128;
    if (m0 >= cnt) return;
    int n0 = blockIdx.x * 64;

    const f16 *Bg, *Bu;
    f16 *D;
    int ldb, ldc;
    if (mode) {
        long wb = (long)e * H_DIM * I_DIM;
        Bg = Wg_ + wb; Bu = Wu_ + wb;
        D = act_; ldb = I_DIM; ldc = I_DIM;
    } else {
        Bg = Sg_; Bu = Su_;
        D = sact_; ldb = IS_DIM; ldc = IS_DIM;
    }

    extern __shared__ f16 smem_[];
    f16* sA  = smem_;
    f16* sBg = smem_ + NSTAGE * SA_STAGE;
    f16* sBu = sBg  + NSTAGE * SD_STAGE;

    const int tid = threadIdx.x;
    const int lane = tid & 31, wid = tid >> 5;
    const int wm = wid & 3, wn = wid >> 2;
    const int ar = tid >> 1, ac = (tid & 1) << 4;
    const int br = tid >> 3, bc = (tid & 7) << 3;

    int mrow = m0 + ar; if (mrow >= cnt) mrow = cnt - 1;
    int rowidx = mode ? g_tok[e * T_TOK + mrow] : mrow;
    long aoff = (long)rowidx * H_DIM + ac;
    long boff = (long)br * ldb + n0 + bc;

    const int kseg = H_DIM >> 5;
    const int nk = 2 * kseg;

    float accg[32], accu[32];
    #pragma unroll
    for (int i = 0; i < 32; i++) { accg[i] = 0.f; accu[i] = 0.f; }

    auto issue = [&](int kb) {
        int s  = kb / kseg;
        int kl = (kb - s * kseg) << 5;
        const f16* ap = (s ? xl_ : xh_) + aoff + kl;
        const f16* gp = Bg + boff + (long)kl * ldb;
        const f16* up = Bu + boff + (long)kl * ldb;
        int st = kb % NSTAGE;
        f16* dA = sA + st * SA_STAGE + ar * SA_LD + ac;
        cp16(dA, ap);
        cp16(dA + 8, ap + 8);
        cp16(sBg + st * SD_STAGE + br * SD_LD + bc, gp);
        cp16(sBu + st * SD_STAGE + br * SD_LD + bc, up);
        CP_COMMIT();
    };

    issue(0);
    issue(1);
    for (int kb = 0; kb < nk; kb++) {
        if (kb + 1 < nk) CP_WAIT1(); else CP_WAIT0();
        __syncthreads();
        if (kb + 2 < nk) issue(kb + 2);
        int st = kb % NSTAGE;
        const f16* cA = sA  + st * SA_STAGE;
        const f16* cG = sBg + st * SD_STAGE;
        const f16* cU = sBu + st * SD_STAGE;
        #pragma unroll
        for (int ks = 0; ks < 2; ks++) {
            uint32_t af[2][4];
            #pragma unroll
            for (int mt = 0; mt < 2; mt++) {
                int row = wm * 32 + mt * 16 + (lane & 15);
                int col = ks * 16 + ((lane >> 4) << 3);
                uint32_t ad = s2u(&cA[row * SA_LD + col]);
                asm volatile("ldmatrix.sync.aligned.m8n8.x4.shared.b16 {%0,%1,%2,%3}, [%4];"
                    : "=r"(af[mt][0]), "=r"(af[mt][1]), "=r"(af[mt][2]), "=r"(af[mt][3])
                    : "r"(ad));
            }
            uint32_t bg[4][2], bu[4][2];
            #pragma unroll
            for (int nt = 0; nt < 2; nt++) {
                int row = ks * 16 + (lane & 15);
                int col = wn * 32 + nt * 16 + ((lane >> 4) << 3);
                uint32_t gd = s2u(&cG[row * SD_LD + col]);
                asm volatile("ldmatrix.sync.aligned.m8n8.x4.trans.shared.b16 {%0,%1,%2,%3}, [%4];"
                    : "=r"(bg[nt*2][0]), "=r"(bg[nt*2][1]),
                      "=r"(bg[nt*2+1][0]), "=r"(bg[nt*2+1][1])
                    : "r"(gd));
                uint32_t ud = s2u(&cU[row * SD_LD + col]);
                asm volatile("ldmatrix.sync.aligned.m8n8.x4.trans.shared.b16 {%0,%1,%2,%3}, [%4];"
                    : "=r"(bu[nt*2][0]), "=r"(bu[nt*2][1]),
                      "=r"(bu[nt*2+1][0]), "=r"(bu[nt*2+1][1])
                    : "r"(ud));
            }
            #pragma unroll
            for (int mt = 0; mt < 2; mt++)
                #pragma unroll
                for (int nt = 0; nt < 4; nt++) {
                    float* cg = accg + (mt * 4 + nt) * 4;
                    asm volatile("mma.sync.aligned.m16n8k16.row.col.f32.f16.f16.f32 "
                        "{%0,%1,%2,%3},{%4,%5,%6,%7},{%8,%9},{%0,%1,%2,%3};"
                        : "+f"(cg[0]), "+f"(cg[1]), "+f"(cg[2]), "+f"(cg[3])
                        : "r"(af[mt][0]), "r"(af[mt][1]), "r"(af[mt][2]), "r"(af[mt][3]),
                          "r"(bg[nt][0]), "r"(bg[nt][1]));
                    float* cu = accu + (mt * 4 + nt) * 4;
                    asm volatile("mma.sync.aligned.m16n8k16.row.col.f32.f16.f16.f32 "
                        "{%0,%1,%2,%3},{%4,%5,%6,%7},{%8,%9},{%0,%1,%2,%3};"
                        : "+f"(cu[0]), "+f"(cu[1]), "+f"(cu[2]), "+f"(cu[3])
                        : "r"(af[mt][0]), "r"(af[mt][1]), "r"(af[mt][2]), "r"(af[mt][3]),
                          "r"(bu[nt][0]), "r"(bu[nt][1]));
                }
        }
    }

    // epilogue: v = [w*] silu(g) * u ; store single fp16.
    #pragma unroll
    for (int mt = 0; mt < 2; mt++) {
        int l0 = wm * 32 + mt * 16 + (lane >> 2);
        int m_a = m0 + l0, m_b = m0 + l0 + 8;
        bool va = m_a < cnt, vb = m_b < cnt;
        float wa = 1.f, wb_ = 1.f;
        if (mode) {
            wa  = va ? g_slotwt[off + m_a] : 0.f;
            wb_ = vb ? g_slotwt[off + m_b] : 0.f;
        }
        #pragma unroll
        for (int nt = 0; nt < 4; nt++) {
            float* cg = accg + (mt * 4 + nt) * 4;
            float* cu = accu + (mt * 4 + nt) * 4;
            int col = n0 + wn * 32 + nt * 8 + ((lane & 3) << 1);
            if (va) {
                float g0 = cg[0], g1 = cg[1];
                float v0 = wa * (g0 / (1.f + expf(-g0))) * cu[0];
                float v1 = wa * (g1 / (1.f + expf(-g1))) * cu[1];
                long r = (long)(off + m_a) * ldc + col;
                *(ushort2*)(D + r) = make_ushort2(f2hu(v0), f2hu(v1));
            }
            if (vb) {
                float g2 = cg[2], g3 = cg[3];
                float v2 = wb_ * (g2 / (1.f + expf(-g2))) * cu[2];
                float v3 = wb_ * (g3 / (1.f + expf(-g3))) * cu[3];
                long r = (long)(off + m_b) * ldc + col;
                *(ushort2*)(D + r) = make_ushort2(f2hu(v2), f2hu(v3));
            }
        }
    }
}

// ============================================================================
// Single-segment GEMM core (down projections). Block 128x128, BK=32,
// cp.async 3-stage ring, ONE barrier per chunk. 8 warps (4M x 2N), warp 32x64.
// ============================================================================
__device__ __forceinline__ void gemm_core(
    const f16* __restrict__ A, long aoff,
    const f16* __restrict__ B, int ldb, long boff,
    int K, float* acc, f16* sA, f16* sB)
{
    const int tid = threadIdx.x;
    const int lane = tid & 31, wid = tid >> 5;
    const int wm = wid & 3, wn = wid >> 2;
    const int ar = tid >> 1, ac = (tid & 1) << 4;
    const int br = tid >> 3, bc = (tid & 7) << 4;
    const int nk = K >> 5;

    auto issue = [&](int kb) {
        int kl = kb << 5;
        const f16* ap = A + aoff + kl;
        const f16* bp = B + boff + (long)kl * ldb;
        int st = kb % NSTAGE;
        f16* dA = sA + st * SA_STAGE + ar * SA_LD + ac;
        cp16(dA, ap);
        cp16(dA + 8, ap + 8);
        f16* dB = sB + st * SB_STAGE + br * SB_LD + bc;
        cp16(dB, bp);
        cp16(dB + 8, bp + 8);
        CP_COMMIT();
    };

    issue(0);
    issue(1);
    for (int kb = 0; kb < nk; kb++) {
        if (kb + 1 < nk) CP_WAIT1(); else CP_WAIT0();
        __syncthreads();
        if (kb + 2 < nk) issue(kb + 2);
        int st = kb % NSTAGE;
        const f16* cA = sA + st * SA_STAGE;
        const f16* cB = sB + st * SB_STAGE;
        #pragma unroll
        for (int ks = 0; ks < 2; ks++) {
            uint32_t af[2][4];
            #pragma unroll
            for (int mt = 0; mt < 2; mt++) {
                int row = wm * 32 + mt * 16 + (lane & 15);
                int col = ks * 16 + ((lane >> 4) << 3);
                uint32_t ad = s2u(&cA[row * SA_LD + col]);
                asm volatile("ldmatrix.sync.aligned.m8n8.x4.shared.b16 {%0,%1,%2,%3}, [%4];"
                    : "=r"(af[mt][0]), "=r"(af[mt][1]), "=r"(af[mt][2]), "=r"(af[mt][3])
                    : "r"(ad));
            }
            uint32_t bfr[8][2];
            #pragma unroll
            for (int nt = 0; nt < 4; nt++) {
                int row = ks * 16 + (lane & 15);
                int col = wn * 64 + nt * 16 + ((lane >> 4) << 3);
                uint32_t bd = s2u(&cB[row * SB_LD + col]);
                asm volatile("ldmatrix.sync.aligned.m8n8.x4.trans.shared.b16 {%0,%1,%2,%3}, [%4];"
                    : "=r"(bfr[nt*2][0]), "=r"(bfr[nt*2][1]),
                      "=r"(bfr[nt*2+1][0]), "=r"(bfr[nt*2+1][1])
                    : "r"(bd));
            }
            #pragma unroll
            for (int mt = 0; mt < 2; mt++)
                #pragma unroll
                for (int nt = 0; nt < 8; nt++) {
                    float* c = acc + (mt * 8 + nt) * 4;
                    asm volatile("mma.sync.aligned.m16n8k16.row.col.f32.f16.f16.f32 "
                        "{%0,%1,%2,%3},{%4,%5,%6,%7},{%8,%9},{%0,%1,%2,%3};"
                        : "+f"(c[0]), "+f"(c[1]), "+f"(c[2]), "+f"(c[3])
                        : "r"(af[mt][0]), "r"(af[mt][1]), "r"(af[mt][2]), "r"(af[mt][3]),
                          "r"(bfr[nt][0]), "r"(bfr[nt][1]));
                }
        }
    }
}

// ---------------- shared expert down GEMM: out = sact @ Sd ------------------
__global__ __launch_bounds__(256) void k_sdown(float* __restrict__ outp) {
    extern __shared__ f16 smem_[];
    f16* sA = smem_;
    f16* sB = smem_ + NSTAGE * SA_STAGE;
    int m0 = blockIdx.y * 128, n0 = blockIdx.x * 128;
    int tid = threadIdx.x;
    int ar = tid >> 1, ac = (tid & 1) << 4;
    int br = tid >> 3, bc = (tid & 7) << 4;
    long aoff = (long)(m0 + ar) * IS_DIM + ac;
    long boff = (long)br * H_DIM + n0 + bc;
    float acc[64];
    #pragma unroll
    for (int i = 0; i < 64; i++) acc[i] = 0.f;

    gemm_core(sact_, aoff, Sd_, H_DIM, boff, IS_DIM, acc, sA, sB);

    int lane = tid & 31, wid = tid >> 5, wm = wid & 3, wn = wid >> 2;
    #pragma unroll
    for (int mt = 0; mt < 2; mt++) {
        int l0 = wm * 32 + mt * 16 + (lane >> 2);
        #pragma unroll
        for (int nt = 0; nt < 8; nt++) {
            float* c = acc + (mt * 8 + nt) * 4;
            int col = n0 + wn * 64 + nt * 8 + ((lane & 3) << 1);
            long r0 = (long)(m0 + l0) * H_DIM + col;
            long r1 = (long)(m0 + l0 + 8) * H_DIM + col;
            outp[r0] = c[0]; outp[r0 + 1] = c[1];
            outp[r1] = c[2]; outp[r1 + 1] = c[3];
        }
    }
}

// ---------------- expert down GEMM (contig slot A, atomic scatter C) --------
__global__ __launch_bounds__(256) void k_edown(float* __restrict__ out) {
    int e = blockIdx.z;
    int cnt = g_cnt[e];
    int m0 = blockIdx.y * 128;
    if (m0 >= cnt) return;
    int off = g_off[e];
    int n0 = blockIdx.x * 128;

    const f16* B = Wd_ + (long)e * I_DIM * H_DIM;

    extern __shared__ f16 smem_[];
    f16* sA = smem_;
    f16* sB = smem_ + NSTAGE * SA_STAGE;
    int tid = threadIdx.x;
    int ar = tid >> 1, ac = (tid & 1) << 4;
    int br = tid >> 3, bc = (tid & 7) << 4;
    int slot = off + m0 + ar; if (slot >= NSLOT) slot = NSLOT - 1;
    long aoff = (long)slot * I_DIM + ac;
    long boff = (long)br * H_DIM + n0 + bc;
    float acc[64];
    #pragma unroll
    for (int i = 0; i < 64; i++) acc[i] = 0.f;

    gemm_core(act_, aoff, B, H_DIM, boff, I_DIM, acc, sA, sB);

    int lane = tid & 31, wid = tid >> 5, wm = wid & 3, wn = wid >> 2;
    #pragma unroll
    for (int mt = 0; mt < 2; mt++) {
        int l0 = wm * 32 + mt * 16 + (lane >> 2);
        int t0 = (m0 + l0)     < cnt ? g_slottok[off + m0 + l0]     : -1;
        int t1 = (m0 + l0 + 8) < cnt ? g_slottok[off + m0 + l0 + 8] : -1;
        #pragma unroll
        for (int nt = 0; nt < 8; nt++) {
            float* c = acc + (mt * 8 + nt) * 4;
            int col = n0 + wn * 64 + nt * 8 + ((lane & 3) << 1);
            if (t0 >= 0) {
                float* d = out + (long)t0 * H_DIM + col;
                atomicAdd(d, c[0]); atomicAdd(d + 1, c[1]);
            }
            if (t1 >= 0) {
                float* d = out + (long)t1 * H_DIM + col;
                atomicAdd(d, c[2]); atomicAdd(d + 1, c[3]);
            }
        }
    }
}

// ---------------- launch ----------------------------------------------------
extern "C" void kernel_launch(void* const* d_in, const int* in_sizes, int n_in,
                              void* d_out, int out_size) {
    const float* x  = (const float*)d_in[0];
    const float* rw = (const float*)d_in[1];
    const float* Wg = (const float*)d_in[2];
    const float* Wu = (const float*)d_in[3];
    const float* Wd = (const float*)d_in[4];
    const float* Sg = (const float*)d_in[5];
    const float* Su = (const float*)d_in[6];
    const float* Sd = (const float*)d_in[7];
    float* out = (float*)d_out;

    cudaFuncSetAttribute(k_gu,    cudaFuncAttributeMaxDynamicSharedMemorySize, GU_SMEM);
    cudaFuncSetAttribute(k_sdown, cudaFuncAttributeMaxDynamicSharedMemorySize, DN_SMEM);
    cudaFuncSetAttribute(k_edown, cudaFuncAttributeMaxDynamicSharedMemorySize, DN_SMEM);

    k_init<<<1, 256>>>(out, out_size);

    k_cvt_x <<<2048, 256>>>(x);
    k_cvt_wg<<<4096, 256>>>(Wg);
    k_cvt_wu<<<4096, 256>>>(Wu);
    k_cvt_wd<<<4096, 256>>>(Wd);
    k_cvt_sg<<<2048, 256>>>(Sg);
    k_cvt_su<<<2048, 256>>>(Su);
    k_cvt_sd<<<2048, 256>>>(Sd);

    k_router<<<T_TOK, 256>>>(x, rw);
    k_off<<<1, 32>>>();
    k_fill<<<N_EXP, 256>>>();

    // fused gate/up + swiglu -> single-fp16 activations
    k_gu<<<dim3(IS_DIM / 64, T_TOK / 128), 256, GU_SMEM>>>(0);              // shared
    k_gu<<<dim3(I_DIM / 64, T_TOK / 128, N_EXP), 256, GU_SMEM>>>(1);        // experts

    // single-segment down projections: shared writes out; experts accumulate
    k_sdown<<<dim3(H_DIM / 128, T_TOK / 128), 256, DN_SMEM>>>(out);
    k_edown<<<dim3(H_DIM / 128, T_TOK / 128, N_EXP), 256, DN_SMEM>>>(out);
}